// round 1
// baseline (speedup 1.0000x reference)
#include <cuda_runtime.h>
#include <math.h>

#define NN 50000
#define EE 800000
#define HH 4
#define CC 64
#define HC 256   // H*C

// ---------------- device scratch (static, no allocs) ----------------
__device__ float  g_feat[(size_t)NN * HC];   // transformed features h [N, H*C] (both layers)
__device__ float  g_x2[(size_t)NN * CC];     // layer-1 output after elu (input to layer 2)
__device__ float4 g_as[NN];                  // alpha_src per node [N,4]
__device__ float4 g_ad[NN];                  // alpha_dst per node [N,4]
__device__ int    g_off[NN + 1];             // CSR offsets by dst
__device__ int    g_counts[NN];
__device__ int    g_cursor[NN];
__device__ int    g_csr[EE];                 // src indices grouped by dst

// ---------------- CSR build ----------------
__global__ void count_kernel(const int* __restrict__ dst) {
    int e = blockIdx.x * blockDim.x + threadIdx.x;
    if (e < EE) atomicAdd(&g_counts[dst[e]], 1);
}

__global__ void scan_kernel() {
    // single block, 1024 threads: exclusive prefix sum of g_counts -> g_off
    __shared__ int sdata[1024];
    int tid = threadIdx.x;
    int total = 0;
    for (int base = 0; base < NN; base += 1024) {
        int v = (base + tid < NN) ? g_counts[base + tid] : 0;
        sdata[tid] = v;
        __syncthreads();
        for (int o = 1; o < 1024; o <<= 1) {
            int t = (tid >= o) ? sdata[tid - o] : 0;
            __syncthreads();
            sdata[tid] += t;
            __syncthreads();
        }
        if (base + tid < NN) g_off[base + tid + 1] = total + sdata[tid];
        total += sdata[1023];
        __syncthreads();
    }
    if (tid == 0) g_off[0] = 0;
}

__global__ void scatter_kernel(const int* __restrict__ ei) {
    int e = blockIdx.x * blockDim.x + threadIdx.x;
    if (e >= EE) return;
    int s = ei[e];
    int d = ei[EE + e];
    int pos = g_off[d] + atomicAdd(&g_cursor[d], 1);
    g_csr[pos] = s;
}

// ---------------- fp32 SGEMM: C[M,256] = A[M,K] @ B[K,256] ----------------
__global__ __launch_bounds__(256) void sgemm128(const float* __restrict__ A,
                                                const float* __restrict__ B,
                                                float* __restrict__ C,
                                                int M, int K) {
    const int Nc = 256;
    __shared__ float As[8][128];
    __shared__ float Bs[8][128];
    int tid = threadIdx.x;
    int brow = blockIdx.y, bcol = blockIdx.x;
    int tRow = tid / 16, tCol = tid % 16;

    float acc[8][8];
#pragma unroll
    for (int i = 0; i < 8; i++)
#pragma unroll
        for (int j = 0; j < 8; j++) acc[i][j] = 0.f;

    int aRow = tid / 2, aCol = (tid % 2) * 4;
    int bRow = tid / 32, bCol = (tid % 32) * 4;
    const float* Ab = A + (size_t)(brow * 128) * K;
    const float* Bb = B + bcol * 128;

    for (int k0 = 0; k0 < K; k0 += 8) {
        float4 av = make_float4(0.f, 0.f, 0.f, 0.f);
        if (brow * 128 + aRow < M)
            av = *(const float4*)(Ab + (size_t)aRow * K + k0 + aCol);
        As[aCol + 0][aRow] = av.x;
        As[aCol + 1][aRow] = av.y;
        As[aCol + 2][aRow] = av.z;
        As[aCol + 3][aRow] = av.w;
        float4 bv = *(const float4*)(Bb + (size_t)(k0 + bRow) * Nc + bCol);
        *(float4*)&Bs[bRow][bCol] = bv;
        __syncthreads();
#pragma unroll
        for (int k = 0; k < 8; k++) {
            float rm[8], rn[8];
#pragma unroll
            for (int i = 0; i < 8; i++) rm[i] = As[k][tRow * 8 + i];
#pragma unroll
            for (int j = 0; j < 8; j++) rn[j] = Bs[k][tCol * 8 + j];
#pragma unroll
            for (int i = 0; i < 8; i++)
#pragma unroll
                for (int j = 0; j < 8; j++) acc[i][j] += rm[i] * rn[j];
        }
        __syncthreads();
    }
#pragma unroll
    for (int i = 0; i < 8; i++) {
        int r = brow * 128 + tRow * 8 + i;
        if (r < M) {
            float* cp = C + (size_t)r * Nc + bcol * 128 + tCol * 8;
            *(float4*)cp       = make_float4(acc[i][0], acc[i][1], acc[i][2], acc[i][3]);
            *(float4*)(cp + 4) = make_float4(acc[i][4], acc[i][5], acc[i][6], acc[i][7]);
        }
    }
}

// ---------------- attention coefficients per node ----------------
__global__ void attn_kernel(const float* __restrict__ h,
                            const float* __restrict__ asrc,
                            const float* __restrict__ adst) {
    int node = blockIdx.x;
    int w = threadIdx.x >> 5, lane = threadIdx.x & 31;
    const float* hp = h + (size_t)node * HC + w * CC;
    float v0 = hp[lane], v1 = hp[lane + 32];
    float s = v0 * asrc[w * CC + lane] + v1 * asrc[w * CC + lane + 32];
    float d = v0 * adst[w * CC + lane] + v1 * adst[w * CC + lane + 32];
#pragma unroll
    for (int o = 16; o; o >>= 1) {
        s += __shfl_xor_sync(0xffffffffu, s, o);
        d += __shfl_xor_sync(0xffffffffu, d, o);
    }
    if (lane == 0) {
        ((float*)g_as)[node * 4 + w] = s;
        ((float*)g_ad)[node * 4 + w] = d;
    }
}

__device__ __forceinline__ float lrelu(float x) { return x > 0.f ? x : 0.2f * x; }

// ---------------- fused segment softmax + aggregate (1 warp / dst node) ----------------
template <bool ELU_OUT>
__global__ __launch_bounds__(256) void aggregate_kernel(const float* __restrict__ hfeat,
                                                        const float* __restrict__ bias,
                                                        float* __restrict__ out) {
    int n = (blockIdx.x * blockDim.x + threadIdx.x) >> 5;
    if (n >= NN) return;
    int lane = threadIdx.x & 31;
    int begin = g_off[n];
    int deg = g_off[n + 1] - begin + 1;  // + implicit self loop (last edge)
    float4 adn = g_ad[n];

    // pass 1: per-head segment max (edges parallel across lanes)
    float m0 = -INFINITY, m1 = -INFINITY, m2 = -INFINITY, m3 = -INFINITY;
    for (int i = lane; i < deg; i += 32) {
        int src = (i == deg - 1) ? n : g_csr[begin + i];
        float4 s = g_as[src];
        m0 = fmaxf(m0, lrelu(s.x + adn.x));
        m1 = fmaxf(m1, lrelu(s.y + adn.y));
        m2 = fmaxf(m2, lrelu(s.z + adn.z));
        m3 = fmaxf(m3, lrelu(s.w + adn.w));
    }
#pragma unroll
    for (int o = 16; o; o >>= 1) {
        m0 = fmaxf(m0, __shfl_xor_sync(0xffffffffu, m0, o));
        m1 = fmaxf(m1, __shfl_xor_sync(0xffffffffu, m1, o));
        m2 = fmaxf(m2, __shfl_xor_sync(0xffffffffu, m2, o));
        m3 = fmaxf(m3, __shfl_xor_sync(0xffffffffu, m3, o));
    }

    // pass 2: exp weights + denominators + message accumulation
    float acc00 = 0.f, acc01 = 0.f, acc10 = 0.f, acc11 = 0.f;
    float acc20 = 0.f, acc21 = 0.f, acc30 = 0.f, acc31 = 0.f;
    float dn0 = 0.f, dn1 = 0.f, dn2 = 0.f, dn3 = 0.f;

    for (int base = 0; base < deg; base += 32) {
        int i = base + lane;
        int src = n;
        float w0 = 0.f, w1 = 0.f, w2 = 0.f, w3 = 0.f;
        if (i < deg) {
            src = (i == deg - 1) ? n : g_csr[begin + i];
            float4 s = g_as[src];
            w0 = __expf(lrelu(s.x + adn.x) - m0);
            w1 = __expf(lrelu(s.y + adn.y) - m1);
            w2 = __expf(lrelu(s.z + adn.z) - m2);
            w3 = __expf(lrelu(s.w + adn.w) - m3);
            dn0 += w0; dn1 += w1; dn2 += w2; dn3 += w3;
        }
        int cnt = min(32, deg - base);
        for (int j = 0; j < cnt; j++) {
            int sj = __shfl_sync(0xffffffffu, src, j);
            float a0 = __shfl_sync(0xffffffffu, w0, j);
            float a1 = __shfl_sync(0xffffffffu, w1, j);
            float a2 = __shfl_sync(0xffffffffu, w2, j);
            float a3 = __shfl_sync(0xffffffffu, w3, j);
            const float* hp = hfeat + (size_t)sj * HC;
            acc00 += a0 * hp[lane];        acc01 += a0 * hp[lane + 32];
            acc10 += a1 * hp[64 + lane];   acc11 += a1 * hp[96 + lane];
            acc20 += a2 * hp[128 + lane];  acc21 += a2 * hp[160 + lane];
            acc30 += a3 * hp[192 + lane];  acc31 += a3 * hp[224 + lane];
        }
    }
#pragma unroll
    for (int o = 16; o; o >>= 1) {
        dn0 += __shfl_xor_sync(0xffffffffu, dn0, o);
        dn1 += __shfl_xor_sync(0xffffffffu, dn1, o);
        dn2 += __shfl_xor_sync(0xffffffffu, dn2, o);
        dn3 += __shfl_xor_sync(0xffffffffu, dn3, o);
    }
    float i0 = 1.f / (dn0 + 1e-16f), i1 = 1.f / (dn1 + 1e-16f);
    float i2 = 1.f / (dn2 + 1e-16f), i3 = 1.f / (dn3 + 1e-16f);

    float r0 = 0.25f * (acc00 * i0 + acc10 * i1 + acc20 * i2 + acc30 * i3) + bias[lane];
    float r1 = 0.25f * (acc01 * i0 + acc11 * i1 + acc21 * i2 + acc31 * i3) + bias[lane + 32];
    if (ELU_OUT) {
        r0 = r0 > 0.f ? r0 : expm1f(r0);
        r1 = r1 > 0.f ? r1 : expm1f(r1);
    }
    out[(size_t)n * CC + lane] = r0;
    out[(size_t)n * CC + 32 + lane] = r1;
}

// ---------------- launch ----------------
extern "C" void kernel_launch(void* const* d_in, const int* in_sizes, int n_in,
                              void* d_out, int out_size) {
    const float* x      = (const float*)d_in[0];
    const int*   ei     = (const int*)d_in[1];
    const float* W1     = (const float*)d_in[2];
    const float* a1s    = (const float*)d_in[3];
    const float* a1d    = (const float*)d_in[4];
    const float* b1     = (const float*)d_in[5];
    const float* W2     = (const float*)d_in[6];
    const float* a2s    = (const float*)d_in[7];
    const float* a2d    = (const float*)d_in[8];
    const float* b2     = (const float*)d_in[9];
    float* out = (float*)d_out;

    void *counts_p, *cursor_p, *feat_p, *x2_p;
    cudaGetSymbolAddress(&counts_p, g_counts);
    cudaGetSymbolAddress(&cursor_p, g_cursor);
    cudaGetSymbolAddress(&feat_p, g_feat);
    cudaGetSymbolAddress(&x2_p, g_x2);
    float* feat = (float*)feat_p;
    float* x2   = (float*)x2_p;

    // CSR build (by destination)
    cudaMemsetAsync(counts_p, 0, NN * sizeof(int));
    count_kernel<<<(EE + 255) / 256, 256>>>(ei + EE);
    scan_kernel<<<1, 1024>>>();
    cudaMemsetAsync(cursor_p, 0, NN * sizeof(int));
    scatter_kernel<<<(EE + 255) / 256, 256>>>(ei);

    dim3 g1(2, (NN + 127) / 128);

    // ---- layer 1 ----
    sgemm128<<<g1, 256>>>(x, W1, feat, NN, 256);
    attn_kernel<<<NN, 128>>>(feat, a1s, a1d);
    aggregate_kernel<true><<<(NN + 7) / 8, 256>>>(feat, b1, x2);

    // ---- layer 2 ----
    sgemm128<<<g1, 256>>>(x2, W2, feat, NN, 64);
    attn_kernel<<<NN, 128>>>(feat, a2s, a2d);
    aggregate_kernel<false><<<(NN + 7) / 8, 256>>>(feat, b2, out);
}

// round 14
// speedup vs baseline: 1.1048x; 1.1048x over previous
#include <cuda_runtime.h>
#include <cuda_bf16.h>
#include <math.h>
#include <stdint.h>

#define NN 50000
#define EE 800000
#define CC 64
#define HC 256   // H*C

// ---------------- device scratch (static, no allocs) ----------------
__device__ float  g_feat[(size_t)NN * HC];
__device__ float  g_x2[(size_t)NN * CC];
__device__ float4 g_as[NN];
__device__ float4 g_ad[NN];
__device__ int    g_off[NN + 1];
__device__ int    g_counts[NN];
__device__ int    g_cursor[NN];
__device__ int    g_csr[EE];
__device__ __nv_bfloat16 g_Ahi[(size_t)NN * HC];
__device__ __nv_bfloat16 g_Alo[(size_t)NN * HC];
__device__ __nv_bfloat16 g_Bhi[256 * 256];
__device__ __nv_bfloat16 g_Blo[256 * 256];

// ---------------- CSR build ----------------
__global__ void count_kernel(const int* __restrict__ dst) {
    int e = blockIdx.x * blockDim.x + threadIdx.x;
    if (e < EE) atomicAdd(&g_counts[dst[e]], 1);
}

__global__ void scan_kernel() {
    __shared__ int sdata[1024];
    int tid = threadIdx.x;
    int total = 0;
    for (int base = 0; base < NN; base += 1024) {
        int v = (base + tid < NN) ? g_counts[base + tid] : 0;
        sdata[tid] = v;
        __syncthreads();
        for (int o = 1; o < 1024; o <<= 1) {
            int t = (tid >= o) ? sdata[tid - o] : 0;
            __syncthreads();
            sdata[tid] += t;
            __syncthreads();
        }
        if (base + tid < NN) g_off[base + tid + 1] = total + sdata[tid];
        total += sdata[1023];
        __syncthreads();
    }
    if (tid == 0) g_off[0] = 0;
}

__global__ void scatter_kernel(const int* __restrict__ ei) {
    int e = blockIdx.x * blockDim.x + threadIdx.x;
    if (e >= EE) return;
    int s = ei[e];
    int d = ei[EE + e];
    int pos = g_off[d] + atomicAdd(&g_cursor[d], 1);
    g_csr[pos] = s;
}

// ---------------- bf16 split conversions ----------------
__global__ void cvt_split(const float* __restrict__ s, __nv_bfloat16* __restrict__ hi,
                          __nv_bfloat16* __restrict__ lo, int n) {
    int i = blockIdx.x * blockDim.x + threadIdx.x;
    if (i < n) {
        float v = s[i];
        __nv_bfloat16 h = __float2bfloat16(v);
        hi[i] = h;
        lo[i] = __float2bfloat16(v - __bfloat162float(h));
    }
}
// W [K,256] fp32 -> Bt [256,K] bf16 hi/lo (transposed, K-major per output col)
__global__ void cvt_w(const float* __restrict__ W, __nv_bfloat16* __restrict__ hi,
                      __nv_bfloat16* __restrict__ lo, int K) {
    int i = blockIdx.x * blockDim.x + threadIdx.x;
    if (i < K * 256) {
        int k = i >> 8, n = i & 255;
        float v = W[i];
        __nv_bfloat16 h = __float2bfloat16(v);
        hi[n * K + k] = h;
        lo[n * K + k] = __float2bfloat16(v - __bfloat162float(h));
    }
}

// ---------------- bf16x3 mma.sync GEMM: C[NN,256] = A[NN,KTOT] @ Bt^T ----------------
// A row-major [NN, KTOT] (hi/lo). Bt row-major [256, KTOT] (hi/lo; row n = W column n).
// CTA: 128x128 tile, 8 warps (warp = 32 rows x 64 cols). K chunk = 32.
__device__ __forceinline__ void mma_bf16(float* d, const uint32_t* a, const uint32_t* b) {
    asm volatile(
        "mma.sync.aligned.m16n8k16.row.col.f32.bf16.bf16.f32 "
        "{%0,%1,%2,%3}, {%4,%5,%6,%7}, {%8,%9}, {%0,%1,%2,%3};"
        : "+f"(d[0]), "+f"(d[1]), "+f"(d[2]), "+f"(d[3])
        : "r"(a[0]), "r"(a[1]), "r"(a[2]), "r"(a[3]), "r"(b[0]), "r"(b[1]));
}

template <int KTOT>
__global__ __launch_bounds__(256, 1)
void mm_mma(const __nv_bfloat16* __restrict__ Ahi, const __nv_bfloat16* __restrict__ Alo,
            const __nv_bfloat16* __restrict__ Bhi, const __nv_bfloat16* __restrict__ Blo,
            float* __restrict__ C)
{
    constexpr int KC = 32;
    constexpr int NCH = KTOT / KC;
    constexpr int LDS_ = 40;  // row stride (bf16): 80B, 16B-aligned, conflict-free frags
    __shared__ __nv_bfloat16 sAh[128][LDS_], sAl[128][LDS_];
    __shared__ __nv_bfloat16 sBh[128][LDS_], sBl[128][LDS_];

    int tid = threadIdx.x, w = tid >> 5, L = tid & 31;
    int wr = w & 3, wc = w >> 2;          // warp grid 4 x 2
    int g = L >> 2, tg = L & 3;           // fragment thread coords
    int r0 = blockIdx.y * 128, cb = blockIdx.x * 128;

    float acc[2][8][4];
#pragma unroll
    for (int i = 0; i < 2; i++)
#pragma unroll
        for (int j = 0; j < 8; j++)
#pragma unroll
            for (int q = 0; q < 4; q++) acc[i][j][q] = 0.f;

    for (int c = 0; c < NCH; c++) {
        int kb = c * KC;
        // stage A (128 rows x 32 k) and B (128 n-rows x 32 k), hi+lo
        for (int idx = tid; idx < 128 * 4; idx += 256) {
            int r = idx >> 2, q = idx & 3;
            int gr = r0 + r;
            uint4 vh = make_uint4(0, 0, 0, 0), vl = vh;
            if (gr < NN) {
                size_t gi = (size_t)gr * KTOT + kb + q * 8;
                vh = *(const uint4*)(Ahi + gi);
                vl = *(const uint4*)(Alo + gi);
            }
            *(uint4*)&sAh[r][q * 8] = vh;
            *(uint4*)&sAl[r][q * 8] = vl;
            size_t bi = (size_t)(cb + r) * KTOT + kb + q * 8;
            *(uint4*)&sBh[r][q * 8] = *(const uint4*)(Bhi + bi);
            *(uint4*)&sBl[r][q * 8] = *(const uint4*)(Blo + bi);
        }
        __syncthreads();

#pragma unroll
        for (int t = 0; t < 2; t++) {
            int k0 = t * 16;
            uint32_t ah[2][4], al[2][4], bh[8][2], bl[8][2];
#pragma unroll
            for (int i = 0; i < 2; i++) {
                int rb = wr * 32 + i * 16;
                ah[i][0] = *(const uint32_t*)&sAh[rb + g][k0 + tg * 2];
                ah[i][1] = *(const uint32_t*)&sAh[rb + g + 8][k0 + tg * 2];
                ah[i][2] = *(const uint32_t*)&sAh[rb + g][k0 + tg * 2 + 8];
                ah[i][3] = *(const uint32_t*)&sAh[rb + g + 8][k0 + tg * 2 + 8];
                al[i][0] = *(const uint32_t*)&sAl[rb + g][k0 + tg * 2];
                al[i][1] = *(const uint32_t*)&sAl[rb + g + 8][k0 + tg * 2];
                al[i][2] = *(const uint32_t*)&sAl[rb + g][k0 + tg * 2 + 8];
                al[i][3] = *(const uint32_t*)&sAl[rb + g + 8][k0 + tg * 2 + 8];
            }
#pragma unroll
            for (int j = 0; j < 8; j++) {
                int n = wc * 64 + j * 8 + g;
                bh[j][0] = *(const uint32_t*)&sBh[n][k0 + tg * 2];
                bh[j][1] = *(const uint32_t*)&sBh[n][k0 + tg * 2 + 8];
                bl[j][0] = *(const uint32_t*)&sBl[n][k0 + tg * 2];
                bl[j][1] = *(const uint32_t*)&sBl[n][k0 + tg * 2 + 8];
            }
#pragma unroll
            for (int i = 0; i < 2; i++)
#pragma unroll
                for (int j = 0; j < 8; j++) {
                    mma_bf16(acc[i][j], ah[i], bh[j]);
                    mma_bf16(acc[i][j], ah[i], bl[j]);
                    mma_bf16(acc[i][j], al[i], bh[j]);
                }
        }
        __syncthreads();
    }

    // epilogue
#pragma unroll
    for (int i = 0; i < 2; i++) {
        int rbase = r0 + wr * 32 + i * 16 + g;
#pragma unroll
        for (int j = 0; j < 8; j++) {
            int col = cb + wc * 64 + j * 8 + tg * 2;
            if (rbase < NN)
                *(float2*)(C + (size_t)rbase * 256 + col) = make_float2(acc[i][j][0], acc[i][j][1]);
            if (rbase + 8 < NN)
                *(float2*)(C + (size_t)(rbase + 8) * 256 + col) = make_float2(acc[i][j][2], acc[i][j][3]);
        }
    }
}

// ---------------- attention coefficients per node ----------------
__global__ void attn_kernel(const float* __restrict__ h,
                            const float* __restrict__ asrc,
                            const float* __restrict__ adst) {
    int node = blockIdx.x;
    int w = threadIdx.x >> 5, lane = threadIdx.x & 31;
    const float* hp = h + (size_t)node * HC + w * CC;
    float v0 = hp[lane], v1 = hp[lane + 32];
    float s = v0 * asrc[w * CC + lane] + v1 * asrc[w * CC + lane + 32];
    float d = v0 * adst[w * CC + lane] + v1 * adst[w * CC + lane + 32];
#pragma unroll
    for (int o = 16; o; o >>= 1) {
        s += __shfl_xor_sync(0xffffffffu, s, o);
        d += __shfl_xor_sync(0xffffffffu, d, o);
    }
    if (lane == 0) {
        ((float*)g_as)[node * 4 + w] = s;
        ((float*)g_ad)[node * 4 + w] = d;
    }
}

__device__ __forceinline__ float lrelu(float x) { return x > 0.f ? x : 0.2f * x; }

// ---------------- fused segment softmax + aggregate (1 warp / dst node) ----------------
template <bool ELU_OUT, bool SPLIT>
__global__ __launch_bounds__(256) void aggregate_kernel(const float* __restrict__ hfeat,
                                                        const float* __restrict__ bias,
                                                        float* __restrict__ out,
                                                        __nv_bfloat16* __restrict__ ahi,
                                                        __nv_bfloat16* __restrict__ alo) {
    int n = (blockIdx.x * blockDim.x + threadIdx.x) >> 5;
    if (n >= NN) return;
    int lane = threadIdx.x & 31;
    int begin = g_off[n];
    int deg = g_off[n + 1] - begin + 1;  // + implicit self loop (last edge)
    float4 adn = g_ad[n];

    float m0 = -INFINITY, m1 = -INFINITY, m2 = -INFINITY, m3 = -INFINITY;
    for (int i = lane; i < deg; i += 32) {
        int src = (i == deg - 1) ? n : g_csr[begin + i];
        float4 s = g_as[src];
        m0 = fmaxf(m0, lrelu(s.x + adn.x));
        m1 = fmaxf(m1, lrelu(s.y + adn.y));
        m2 = fmaxf(m2, lrelu(s.z + adn.z));
        m3 = fmaxf(m3, lrelu(s.w + adn.w));
    }
#pragma unroll
    for (int o = 16; o; o >>= 1) {
        m0 = fmaxf(m0, __shfl_xor_sync(0xffffffffu, m0, o));
        m1 = fmaxf(m1, __shfl_xor_sync(0xffffffffu, m1, o));
        m2 = fmaxf(m2, __shfl_xor_sync(0xffffffffu, m2, o));
        m3 = fmaxf(m3, __shfl_xor_sync(0xffffffffu, m3, o));
    }

    float acc00 = 0.f, acc01 = 0.f, acc10 = 0.f, acc11 = 0.f;
    float acc20 = 0.f, acc21 = 0.f, acc30 = 0.f, acc31 = 0.f;
    float dn0 = 0.f, dn1 = 0.f, dn2 = 0.f, dn3 = 0.f;

    for (int base = 0; base < deg; base += 32) {
        int i = base + lane;
        int src = n;
        float w0 = 0.f, w1 = 0.f, w2 = 0.f, w3 = 0.f;
        if (i < deg) {
            src = (i == deg - 1) ? n : g_csr[begin + i];
            float4 s = g_as[src];
            w0 = __expf(lrelu(s.x + adn.x) - m0);
            w1 = __expf(lrelu(s.y + adn.y) - m1);
            w2 = __expf(lrelu(s.z + adn.z) - m2);
            w3 = __expf(lrelu(s.w + adn.w) - m3);
            dn0 += w0; dn1 += w1; dn2 += w2; dn3 += w3;
        }
        int cnt = min(32, deg - base);
        for (int j = 0; j < cnt; j++) {
            int sj = __shfl_sync(0xffffffffu, src, j);
            float a0 = __shfl_sync(0xffffffffu, w0, j);
            float a1 = __shfl_sync(0xffffffffu, w1, j);
            float a2 = __shfl_sync(0xffffffffu, w2, j);
            float a3 = __shfl_sync(0xffffffffu, w3, j);
            const float* hp = hfeat + (size_t)sj * HC;
            acc00 += a0 * hp[lane];        acc01 += a0 * hp[lane + 32];
            acc10 += a1 * hp[64 + lane];   acc11 += a1 * hp[96 + lane];
            acc20 += a2 * hp[128 + lane];  acc21 += a2 * hp[160 + lane];
            acc30 += a3 * hp[192 + lane];  acc31 += a3 * hp[224 + lane];
        }
    }
#pragma unroll
    for (int o = 16; o; o >>= 1) {
        dn0 += __shfl_xor_sync(0xffffffffu, dn0, o);
        dn1 += __shfl_xor_sync(0xffffffffu, dn1, o);
        dn2 += __shfl_xor_sync(0xffffffffu, dn2, o);
        dn3 += __shfl_xor_sync(0xffffffffu, dn3, o);
    }
    float i0 = 1.f / (dn0 + 1e-16f), i1 = 1.f / (dn1 + 1e-16f);
    float i2 = 1.f / (dn2 + 1e-16f), i3 = 1.f / (dn3 + 1e-16f);

    float r0 = 0.25f * (acc00 * i0 + acc10 * i1 + acc20 * i2 + acc30 * i3) + bias[lane];
    float r1 = 0.25f * (acc01 * i0 + acc11 * i1 + acc21 * i2 + acc31 * i3) + bias[lane + 32];
    if (ELU_OUT) {
        r0 = r0 > 0.f ? r0 : expm1f(r0);
        r1 = r1 > 0.f ? r1 : expm1f(r1);
    }
    out[(size_t)n * CC + lane] = r0;
    out[(size_t)n * CC + 32 + lane] = r1;
    if (SPLIT) {  // fused bf16 hi/lo split for next layer's GEMM A
        __nv_bfloat16 h0 = __float2bfloat16(r0);
        __nv_bfloat16 h1 = __float2bfloat16(r1);
        ahi[(size_t)n * CC + lane] = h0;
        ahi[(size_t)n * CC + 32 + lane] = h1;
        alo[(size_t)n * CC + lane] = __float2bfloat16(r0 - __bfloat162float(h0));
        alo[(size_t)n * CC + 32 + lane] = __float2bfloat16(r1 - __bfloat162float(h1));
    }
}

// ---------------- launch ----------------
extern "C" void kernel_launch(void* const* d_in, const int* in_sizes, int n_in,
                              void* d_out, int out_size) {
    const float* x   = (const float*)d_in[0];
    const int*   ei  = (const int*)d_in[1];
    const float* W1  = (const float*)d_in[2];
    const float* a1s = (const float*)d_in[3];
    const float* a1d = (const float*)d_in[4];
    const float* b1  = (const float*)d_in[5];
    const float* W2  = (const float*)d_in[6];
    const float* a2s = (const float*)d_in[7];
    const float* a2d = (const float*)d_in[8];
    const float* b2  = (const float*)d_in[9];
    float* out = (float*)d_out;

    void *counts_p, *cursor_p, *feat_p, *x2_p, *ahi_p, *alo_p, *bhi_p, *blo_p;
    cudaGetSymbolAddress(&counts_p, g_counts);
    cudaGetSymbolAddress(&cursor_p, g_cursor);
    cudaGetSymbolAddress(&feat_p, g_feat);
    cudaGetSymbolAddress(&x2_p, g_x2);
    cudaGetSymbolAddress(&ahi_p, g_Ahi);
    cudaGetSymbolAddress(&alo_p, g_Alo);
    cudaGetSymbolAddress(&bhi_p, g_Bhi);
    cudaGetSymbolAddress(&blo_p, g_Blo);
    float* feat = (float*)feat_p;
    float* x2   = (float*)x2_p;
    __nv_bfloat16* Ahi = (__nv_bfloat16*)ahi_p;
    __nv_bfloat16* Alo = (__nv_bfloat16*)alo_p;
    __nv_bfloat16* Bhi = (__nv_bfloat16*)bhi_p;
    __nv_bfloat16* Blo = (__nv_bfloat16*)blo_p;

    // CSR build (by destination)
    cudaMemsetAsync(counts_p, 0, NN * sizeof(int));
    count_kernel<<<(EE + 255) / 256, 256>>>(ei + EE);
    scan_kernel<<<1, 1024>>>();
    cudaMemsetAsync(cursor_p, 0, NN * sizeof(int));
    scatter_kernel<<<(EE + 255) / 256, 256>>>(ei);

    dim3 gg(2, (NN + 127) / 128);  // N tiles x M tiles

    // ---- layer 1 ----
    cvt_split<<<(NN * HC + 255) / 256, 256>>>(x, Ahi, Alo, NN * HC);
    cvt_w<<<(256 * 256 + 255) / 256, 256>>>(W1, Bhi, Blo, 256);
    mm_mma<256><<<gg, 256>>>(Ahi, Alo, Bhi, Blo, feat);
    attn_kernel<<<NN, 128>>>(feat, a1s, a1d);
    aggregate_kernel<true, true><<<(NN + 7) / 8, 256>>>(feat, b1, x2, Ahi, Alo);

    // ---- layer 2 ----
    cvt_w<<<(64 * 256 + 255) / 256, 256>>>(W2, Bhi, Blo, 64);
    mm_mma<64><<<gg, 256>>>(Ahi, Alo, Bhi, Blo, feat);
    attn_kernel<<<NN, 128>>>(feat, a2s, a2d);
    aggregate_kernel<false, false><<<(NN + 7) / 8, 256>>>(feat, b2, out, nullptr, nullptr);
}